// round 14
// baseline (speedup 1.0000x reference)
#include <cuda_runtime.h>
#include <cuda_bf16.h>
#include <cstdint>
#include <cstddef>

#define NN   50000
#define EE   800000
#define INC  128
#define OUTC 256
#define HALF 128
#define NR   6
#define NB   (NN * NR)            // 300000 buckets (node, rel)
#define NBLK ((NB + 4095) / 4096) // 74 scan blocks

// ---------------- scratch (module-scope device memory; no allocations) ------
__device__ __align__(16) __nv_bfloat16 d_xh [(size_t)NN * INC];
__device__ __align__(16) __nv_bfloat16 d_xl [(size_t)NN * INC];
__device__ __align__(16) __nv_bfloat16 d_h1h[(size_t)NN * OUTC];
__device__ __align__(16) __nv_bfloat16 d_h1l[(size_t)NN * OUTC];
__device__ __align__(16) __nv_bfloat16 d_h2h[(size_t)NN * OUTC];
__device__ __align__(16) __nv_bfloat16 d_h2l[(size_t)NN * OUTC];
__device__ __align__(16) __nv_bfloat16 d_g1h[(size_t)NN * OUTC];
__device__ __align__(16) __nv_bfloat16 d_g1l[(size_t)NN * OUTC];
__device__ __align__(16) __nv_bfloat16 d_g2h[(size_t)NN * OUTC];
__device__ __align__(16) __nv_bfloat16 d_g2l[(size_t)NN * OUTC];
__device__ __align__(16) __nv_bfloat16 d_acch[(size_t)NN * NR * OUTC];
__device__ __align__(16) __nv_bfloat16 d_accl[(size_t)NN * NR * OUTC];
__device__ int   d_cnt[NB];
__device__ int   d_off[NB];
__device__ int   d_cur[NB];
__device__ int   d_csr[EE];
__device__ int   d_bsum[128];
__device__ float d_inv[NB];
__device__ __align__(16) __nv_bfloat16 d_bh[1048576];
__device__ __align__(16) __nv_bfloat16 d_bl[1048576];

// ---------------- helpers (sm_80+ family-wide; no sm_103a-only ISA) ---------
__device__ __forceinline__ uint32_t smem_u32(const void* p) {
    uint32_t a;
    asm("{ .reg .u64 t; cvta.to.shared.u64 t, %1; cvt.u32.u64 %0, t; }" : "=r"(a) : "l"(p));
    return a;
}
__device__ __forceinline__ void ldsm4(uint32_t* r, uint32_t addr) {
    asm volatile("ldmatrix.sync.aligned.m8n8.x4.shared.b16 {%0,%1,%2,%3}, [%4];"
        : "=r"(r[0]), "=r"(r[1]), "=r"(r[2]), "=r"(r[3]) : "r"(addr));
}
__device__ __forceinline__ void mma16816(float* c, const uint32_t* a, const uint32_t* b) {
    asm volatile("mma.sync.aligned.m16n8k16.row.col.f32.bf16.bf16.f32 "
        "{%0,%1,%2,%3}, {%4,%5,%6,%7}, {%8,%9}, {%0,%1,%2,%3};"
        : "+f"(c[0]), "+f"(c[1]), "+f"(c[2]), "+f"(c[3])
        : "r"(a[0]), "r"(a[1]), "r"(a[2]), "r"(a[3]), "r"(b[0]), "r"(b[1]));
}
#define CPA16(dst, src) \
    asm volatile("cp.async.cg.shared.global [%0], [%1], 16;" :: "r"(dst), "l"(src) : "memory")
#define CP_COMMIT()  asm volatile("cp.async.commit_group;" ::: "memory")
#define CP_WAIT1()   asm volatile("cp.async.wait_group 1;" ::: "memory")
#define CP_WAIT0()   asm volatile("cp.async.wait_group 0;" ::: "memory")

// ---------------- all-bf16 cp.async 3-stage bf16x3 GEMM ----------------------
#define STG 32768
#define GSMEM (3 * STG)

__global__ void __launch_bounds__(256, 2)
gemm_cp(const __nv_bfloat16* __restrict__ Ah0, const __nv_bfloat16* __restrict__ Al0,
        int d0, int ld0,
        const __nv_bfloat16* __restrict__ Ah1, const __nv_bfloat16* __restrict__ Al1,
        int ld1,
        const __nv_bfloat16* __restrict__ Bh, const __nv_bfloat16* __restrict__ Bl,
        const float* __restrict__ bias,
        float* __restrict__ Cf, __nv_bfloat16* __restrict__ Ch, __nv_bfloat16* __restrict__ Cl,
        int ldc, int M, int K, int relu)
{
    extern __shared__ char sm[];
    const uint32_t sb = smem_u32(sm);
    const int tid  = threadIdx.x;
    const int lane = tid & 31;
    const int w    = tid >> 5;
    const int wm   = w & 3;
    const int wn   = w >> 2;
    const int row0 = blockIdx.y * 128;
    const int n0   = blockIdx.x * 128;
    const int nIter = K / 32;

    float acc[2][8][4];
#pragma unroll
    for (int i = 0; i < 2; i++)
#pragma unroll
        for (int j = 0; j < 8; j++)
#pragma unroll
            for (int q = 0; q < 4; q++) acc[i][j][q] = 0.f;

    auto issue = [&](int s, uint32_t base) {
        int cb = s * 32;
        const __nv_bfloat16 *pAh, *pAl; int ld;
        if (cb < d0) { pAh = Ah0; pAl = Al0; ld = ld0; }
        else         { pAh = Ah1; pAl = Al1; ld = ld1; cb -= d0; }
#pragma unroll
        for (int j = 0; j < 2; j++) {
            int idx = tid + j * 256;              // 512 chunks (128 rows x 4)
            int r = idx >> 2, c = idx & 3;
            uint32_t so = (uint32_t)(r * 64 + ((c ^ ((r >> 1) & 3)) << 4));
            int gr = row0 + r; if (gr >= M) gr = M - 1;
            size_t ga = (size_t)gr * ld + cb + c * 8;
            CPA16(base + so,        pAh + ga);
            CPA16(base + 8192 + so, pAl + ga);
        }
        const int kb = s * 32;
#pragma unroll
        for (int j = 0; j < 2; j++) {
            int idx = tid + j * 256;
            int r = idx >> 2, c = idx & 3;
            uint32_t so = (uint32_t)(r * 64 + ((c ^ ((r >> 1) & 3)) << 4));
            size_t ga = (size_t)(n0 + r) * K + kb + c * 8;
            CPA16(base + 16384 + so, Bh + ga);
            CPA16(base + 24576 + so, Bl + ga);
        }
        CP_COMMIT();
    };

    issue(0, sb);
    if (nIter > 1) issue(1, sb + STG);

    const int aR   = lane & 15;
    const int aSwz = (lane >> 1) & 3;
    const int aCof = lane >> 4;
    const int bR   = (lane & 7) + ((lane >> 4) << 3);
    const int bSwz = (bR >> 1) & 3;
    const int bCof = (lane >> 3) & 1;

    int st = 0, stNxt = (nIter > 2) ? 2 : 0;
    for (int s = 0; s < nIter; s++) {
        if (s + 1 < nIter) CP_WAIT1(); else CP_WAIT0();
        __syncthreads();
        if (s + 2 < nIter) {
            issue(s + 2, sb + (uint32_t)stNxt * STG);
            stNxt = (stNxt + 1 == 3) ? 0 : stNxt + 1;
        }
        const uint32_t base = sb + (uint32_t)st * STG;
        st = (st + 1 == 3) ? 0 : st + 1;
#pragma unroll
        for (int kk = 0; kk < 32; kk += 16) {
            const int ckk = kk >> 3;
            uint32_t ah[2][4], al[2][4];
#pragma unroll
            for (int mi = 0; mi < 2; mi++) {
                int row = wm * 32 + mi * 16 + aR;
                uint32_t so = (uint32_t)(row * 64 + (((ckk + aCof) ^ aSwz) << 4));
                ldsm4(ah[mi], base + so);
                ldsm4(al[mi], base + 8192 + so);
            }
#pragma unroll
            for (int j2 = 0; j2 < 4; j2++) {
                int row = wn * 64 + j2 * 16 + bR;
                uint32_t so = (uint32_t)(row * 64 + (((ckk + bCof) ^ bSwz) << 4));
                uint32_t bhf[4], blf[4];
                ldsm4(bhf, base + 16384 + so);
                ldsm4(blf, base + 24576 + so);
#pragma unroll
                for (int mi = 0; mi < 2; mi++)
#pragma unroll
                    for (int nj = 0; nj < 2; nj++) {
                        float* c = acc[mi][j2 * 2 + nj];
                        mma16816(c, ah[mi], bhf + nj * 2);
                        mma16816(c, al[mi], bhf + nj * 2);
                        mma16816(c, ah[mi], blf + nj * 2);
                    }
            }
        }
    }

    // ---- epilogue ----
    const int g  = lane >> 2;
    const int tg = lane & 3;
#pragma unroll
    for (int mi = 0; mi < 2; mi++) {
        int r0 = row0 + wm * 32 + mi * 16 + g;
#pragma unroll
        for (int j = 0; j < 8; j++) {
            int gc = n0 + wn * 64 + j * 8 + tg * 2;
            float b0 = bias[gc], b1 = bias[gc + 1];
            float2 v0 = make_float2(acc[mi][j][0] + b0, acc[mi][j][1] + b1);
            float2 v1 = make_float2(acc[mi][j][2] + b0, acc[mi][j][3] + b1);
            if (relu) {
                v0.x = fmaxf(v0.x, 0.f); v0.y = fmaxf(v0.y, 0.f);
                v1.x = fmaxf(v1.x, 0.f); v1.y = fmaxf(v1.y, 0.f);
            }
#pragma unroll
            for (int h = 0; h < 2; h++) {
                int rr = r0 + h * 8;
                if (rr >= M) continue;
                float2 v = h ? v1 : v0;
                size_t o = (size_t)rr * ldc + gc;
                if (Cf) *(float2*)(Cf + o) = v;
                if (Ch) {
                    __nv_bfloat16 hx = __float2bfloat16(v.x), hy = __float2bfloat16(v.y);
                    __nv_bfloat162 hp = {hx, hy};
                    __nv_bfloat162 lp = {__float2bfloat16(v.x - __bfloat162float(hx)),
                                         __float2bfloat16(v.y - __bfloat162float(hy))};
                    *(__nv_bfloat162*)(Ch + o) = hp;
                    *(__nv_bfloat162*)(Cl + o) = lp;
                }
            }
        }
    }
}

// ---------------- fp32 -> bf16 hi/lo split (for x) ---------------------------
__global__ void split_k(const float* __restrict__ X, long n,
                        __nv_bfloat16* __restrict__ xh, __nv_bfloat16* __restrict__ xl)
{
    long i = blockIdx.x * (long)blockDim.x + threadIdx.x;
    if (i >= n) return;
    float v = X[i];
    __nv_bfloat16 hi = __float2bfloat16(v);
    xh[i] = hi;
    xl[i] = __float2bfloat16(v - __bfloat162float(hi));
}

// ---------------- fused weight convert: 6 (possibly stacked) matrices -------
// Logical source row k: k < Ka -> a[k][n], else b[k-Ka][n] (both [*][N]
// row-major).  Output hi/lo bf16 [N][Ktot].  Replaces the former fp32
// staging memcpys (wc1/wc2/wc3) entirely.
struct WDesc { const float* a; const float* b; int Ka; int Ktot; int N; long dstOff; };
struct WDesc6 { WDesc w[6]; };

__global__ void convall_k(WDesc6 d, __nv_bfloat16* __restrict__ bh,
                          __nv_bfloat16* __restrict__ bl)
{
    const WDesc wd = d.w[blockIdx.y];
    const int tot = wd.Ktot * wd.N;
    for (int idx = blockIdx.x * blockDim.x + threadIdx.x; idx < tot;
         idx += gridDim.x * blockDim.x) {
        int n = idx / wd.Ktot, k = idx % wd.Ktot;
        float v = (k < wd.Ka) ? wd.a[(size_t)k * wd.N + n]
                              : wd.b[(size_t)(k - wd.Ka) * wd.N + n];
        __nv_bfloat16 hi = __float2bfloat16(v);
        bh[wd.dstOff + idx] = hi;
        bl[wd.dstOff + idx] = __float2bfloat16(v - __bfloat162float(hi));
    }
}

// ---------------- (node,rel)-CSR build (proven) ------------------------------
__global__ void count_k(const int* __restrict__ dst, const int* __restrict__ et,
                        int E, int* __restrict__ cnt)
{
    int e = blockIdx.x * blockDim.x + threadIdx.x;
    if (e < E) atomicAdd(&cnt[dst[e] * NR + et[e]], 1);
}
__global__ void inv_k(const int* __restrict__ cnt, float* __restrict__ inv, int n)
{
    int i = blockIdx.x * blockDim.x + threadIdx.x;
    if (i < n) { int c = cnt[i]; inv[i] = 1.0f / (float)(c > 1 ? c : 1); }
}
__global__ void scan1_k(const int* __restrict__ cnt, int* __restrict__ bsum)
{
    __shared__ int sh[1024];
    int t = threadIdx.x;
    int i4 = blockIdx.x * 1024 + t;
    int s = 0;
    if (i4 * 4 < NB) {
        int4 v = ((const int4*)cnt)[i4];
        s = v.x + v.y + v.z + v.w;
    }
    sh[t] = s; __syncthreads();
    for (int o = 512; o > 0; o >>= 1) {
        if (t < o) sh[t] += sh[t + o];
        __syncthreads();
    }
    if (t == 0) bsum[blockIdx.x] = sh[0];
}
__global__ void scan2_k(int* __restrict__ bsum, int n)
{
    __shared__ int sh[128];
    int t = threadIdx.x;
    int v = (t < n) ? bsum[t] : 0;
    sh[t] = v; __syncthreads();
    for (int o = 1; o < 128; o <<= 1) {
        int u = (t >= o) ? sh[t - o] : 0;
        __syncthreads();
        sh[t] += u;
        __syncthreads();
    }
    if (t < n) bsum[t] = sh[t] - v;
}
__global__ void scan3_k(const int* __restrict__ cnt, const int* __restrict__ bsum,
                        int* __restrict__ off)
{
    __shared__ int sh[1024];
    int t = threadIdx.x;
    int i4 = blockIdx.x * 1024 + t;
    int4 v = make_int4(0, 0, 0, 0);
    bool ok = (i4 * 4 < NB);
    if (ok) v = ((const int4*)cnt)[i4];
    int s = v.x + v.y + v.z + v.w;
    sh[t] = s; __syncthreads();
    for (int o = 1; o < 1024; o <<= 1) {
        int u = (t >= o) ? sh[t - o] : 0;
        __syncthreads();
        sh[t] += u;
        __syncthreads();
    }
    int ex = bsum[blockIdx.x] + sh[t] - s;
    if (ok) {
        int4 w;
        w.x = ex;
        w.y = ex + v.x;
        w.z = ex + v.x + v.y;
        w.w = ex + v.x + v.y + v.z;
        ((int4*)off)[i4] = w;
    }
}
__global__ void fill_k(const int* __restrict__ src, const int* __restrict__ dst,
                       const int* __restrict__ et, int E,
                       const int* __restrict__ off, int* __restrict__ cur,
                       int* __restrict__ csr)
{
    int e = blockIdx.x * blockDim.x + threadIdx.x;
    if (e < E) {
        int k = dst[e] * NR + et[e];
        int p = off[k] + atomicAdd(&cur[k], 1);
        csr[p] = src[e];
    }
}

// ---------------- gather aggregation: bf16 hi/lo in, bf16 hi/lo out ----------
template<int D>
__global__ void __launch_bounds__(256)
agg_k(const __nv_bfloat16* __restrict__ xh, const __nv_bfloat16* __restrict__ xl,
      const int* __restrict__ off, const int* __restrict__ cnt,
      const float* __restrict__ inv, const int* __restrict__ csr,
      __nv_bfloat16* __restrict__ acch, __nv_bfloat16* __restrict__ accl)
{
    constexpr int T   = D / 4;
    constexpr int NPB = 256 / T;
    const int node = blockIdx.x * NPB + threadIdx.x / T;
    const int c4   = (threadIdx.x % T) * 4;
    if (node >= NN) return;
    const size_t base = (size_t)node * NR * D + c4;
#pragma unroll
    for (int r = 0; r < NR; r++) {
        const int b = node * NR + r;
        const int o = off[b], c = cnt[b];
        float a0 = 0.f, a1 = 0.f, a2 = 0.f, a3 = 0.f;
        int e = 0;
        for (; e + 2 <= c; e += 2) {
            int s0 = __ldg(&csr[o + e]);
            int s1 = __ldg(&csr[o + e + 1]);
            size_t p0 = (size_t)s0 * D + c4, p1 = (size_t)s1 * D + c4;
            uint2 h0 = __ldg((const uint2*)(xh + p0));
            uint2 l0 = __ldg((const uint2*)(xl + p0));
            uint2 h1 = __ldg((const uint2*)(xh + p1));
            uint2 l1 = __ldg((const uint2*)(xl + p1));
            float2 ha = __bfloat1622float2(*(__nv_bfloat162*)&h0.x);
            float2 hb = __bfloat1622float2(*(__nv_bfloat162*)&h0.y);
            float2 la = __bfloat1622float2(*(__nv_bfloat162*)&l0.x);
            float2 lb = __bfloat1622float2(*(__nv_bfloat162*)&l0.y);
            a0 += ha.x + la.x; a1 += ha.y + la.y; a2 += hb.x + lb.x; a3 += hb.y + lb.y;
            ha = __bfloat1622float2(*(__nv_bfloat162*)&h1.x);
            hb = __bfloat1622float2(*(__nv_bfloat162*)&h1.y);
            la = __bfloat1622float2(*(__nv_bfloat162*)&l1.x);
            lb = __bfloat1622float2(*(__nv_bfloat162*)&l1.y);
            a0 += ha.x + la.x; a1 += ha.y + la.y; a2 += hb.x + lb.x; a3 += hb.y + lb.y;
        }
        if (e < c) {
            int s0 = __ldg(&csr[o + e]);
            size_t p0 = (size_t)s0 * D + c4;
            uint2 h0 = __ldg((const uint2*)(xh + p0));
            uint2 l0 = __ldg((const uint2*)(xl + p0));
            float2 ha = __bfloat1622float2(*(__nv_bfloat162*)&h0.x);
            float2 hb = __bfloat1622float2(*(__nv_bfloat162*)&h0.y);
            float2 la = __bfloat1622float2(*(__nv_bfloat162*)&l0.x);
            float2 lb = __bfloat1622float2(*(__nv_bfloat162*)&l0.y);
            a0 += ha.x + la.x; a1 += ha.y + la.y; a2 += hb.x + lb.x; a3 += hb.y + lb.y;
        }
        const float m = inv[b];
        a0 *= m; a1 *= m; a2 *= m; a3 *= m;
        __nv_bfloat16 q0 = __float2bfloat16(a0), q1 = __float2bfloat16(a1);
        __nv_bfloat16 q2 = __float2bfloat16(a2), q3 = __float2bfloat16(a3);
        uint2 hv, lv;
        *(__nv_bfloat162*)&hv.x = {q0, q1};
        *(__nv_bfloat162*)&hv.y = {q2, q3};
        *(__nv_bfloat162*)&lv.x = {__float2bfloat16(a0 - __bfloat162float(q0)),
                                   __float2bfloat16(a1 - __bfloat162float(q1))};
        *(__nv_bfloat162*)&lv.y = {__float2bfloat16(a2 - __bfloat162float(q2)),
                                   __float2bfloat16(a3 - __bfloat162float(q3))};
        *(uint2*)(acch + base + r * D) = hv;
        *(uint2*)(accl + base + r * D) = lv;
    }
}

// ---------------- launch ------------------------------------------------------
extern "C" void kernel_launch(void* const* d_in, const int* in_sizes, int n_in,
                              void* d_out, int out_size)
{
    const float* x      = (const float*)d_in[0];
    const int*   eidx   = (const int*)  d_in[1];
    const int*   etype  = (const int*)  d_in[2];
    const float* enc_w0 = (const float*)d_in[3];
    const float* enc_b0 = (const float*)d_in[4];
    const float* enc_w1 = (const float*)d_in[5];
    const float* enc_b1 = (const float*)d_in[6];
    const float* enc_w2 = (const float*)d_in[7];
    const float* enc_b2 = (const float*)d_in[8];
    const float* W1     = (const float*)d_in[9];
    const float* root1  = (const float*)d_in[10];
    const float* b1     = (const float*)d_in[11];
    const float* W2     = (const float*)d_in[12];
    const float* root2  = (const float*)d_in[13];
    const float* b2     = (const float*)d_in[14];
    const float* W3     = (const float*)d_in[15];
    const float* root3  = (const float*)d_in[16];
    const float* b3     = (const float*)d_in[17];
    float* out = (float*)d_out;

    const int N = NN, E = EE;
    const int* src = eidx;
    const int* dst = eidx + E;

    float *inv;
    int *cnt, *off, *cur, *csr, *bsum;
    __nv_bfloat16 *bh, *bl, *xh, *xl, *h1h, *h1l, *h2h, *h2l;
    __nv_bfloat16 *g1h, *g1l, *g2h, *g2l, *acch, *accl;
    cudaGetSymbolAddress((void**)&xh,   d_xh);
    cudaGetSymbolAddress((void**)&xl,   d_xl);
    cudaGetSymbolAddress((void**)&h1h,  d_h1h);
    cudaGetSymbolAddress((void**)&h1l,  d_h1l);
    cudaGetSymbolAddress((void**)&h2h,  d_h2h);
    cudaGetSymbolAddress((void**)&h2l,  d_h2l);
    cudaGetSymbolAddress((void**)&g1h,  d_g1h);
    cudaGetSymbolAddress((void**)&g1l,  d_g1l);
    cudaGetSymbolAddress((void**)&g2h,  d_g2h);
    cudaGetSymbolAddress((void**)&g2l,  d_g2l);
    cudaGetSymbolAddress((void**)&acch, d_acch);
    cudaGetSymbolAddress((void**)&accl, d_accl);
    cudaGetSymbolAddress((void**)&cnt,  d_cnt);
    cudaGetSymbolAddress((void**)&off,  d_off);
    cudaGetSymbolAddress((void**)&cur,  d_cur);
    cudaGetSymbolAddress((void**)&csr,  d_csr);
    cudaGetSymbolAddress((void**)&bsum, d_bsum);
    cudaGetSymbolAddress((void**)&inv,  d_inv);
    cudaGetSymbolAddress((void**)&bh,   d_bh);
    cudaGetSymbolAddress((void**)&bl,   d_bl);

    cudaFuncSetAttribute(gemm_cp, cudaFuncAttributeMaxDynamicSharedMemorySize, GSMEM);
    cudaFuncSetAttribute(gemm_cp, cudaFuncAttributePreferredSharedMemoryCarveout, 100);

    const int K1 = (NR + 1) * INC;    // 896
    const int K2 = (NR + 1) * OUTC;   // 1792
    const size_t oE0 = 0;
    const size_t oE1 = oE0 + (size_t)OUTC * INC;
    const size_t oE2 = oE1 + (size_t)OUTC * OUTC;
    const size_t oC1 = oE2 + (size_t)HALF * OUTC;
    const size_t oC2 = oC1 + (size_t)OUTC * K1;
    const size_t oC3 = oC2 + (size_t)OUTC * K2;

    // ---- fork a second stream (capture-safe fork/join; leaked, <= few calls)
    cudaStream_t s2;
    cudaEvent_t evFork, evSplit, evPrep, evEnc;
    cudaStreamCreateWithFlags(&s2, cudaStreamNonBlocking);
    cudaEventCreateWithFlags(&evFork,  cudaEventDisableTiming);
    cudaEventCreateWithFlags(&evSplit, cudaEventDisableTiming);
    cudaEventCreateWithFlags(&evPrep,  cudaEventDisableTiming);
    cudaEventCreateWithFlags(&evEnc,   cudaEventDisableTiming);
    cudaEventRecord(evFork, 0);
    cudaStreamWaitEvent(s2, evFork, 0);

    const dim3 blk(256);
    const int rowTiles = (N + 127) / 128;   // 391

    // ===== stream B: x split first (agg1 dep), weight convert, encoder ======
    split_k<<<(int)(((long)N * INC + 255) / 256), 256, 0, s2>>>(x, (long)N * INC, xh, xl);
    cudaEventRecord(evSplit, s2);     // xh/xl ready

    WDesc6 wd;
    wd.w[0] = {enc_w0, nullptr, INC,  INC,  OUTC, (long)oE0};
    wd.w[1] = {enc_w1, nullptr, OUTC, OUTC, OUTC, (long)oE1};
    wd.w[2] = {enc_w2, nullptr, OUTC, OUTC, HALF, (long)oE2};
    wd.w[3] = {root1,  W1,      INC,  K1,   OUTC, (long)oC1};
    wd.w[4] = {root2,  W2,      OUTC, K2,   OUTC, (long)oC2};
    wd.w[5] = {root3,  W3,      OUTC, K2,   HALF, (long)oC3};
    convall_k<<<dim3(896, 6), blk, 0, s2>>>(wd, bh, bl);
    cudaEventRecord(evPrep, s2);      // all bf16 weights ready

    gemm_cp<<<dim3(2, rowTiles), blk, GSMEM, s2>>>(xh, xl, INC, INC, nullptr, nullptr, 0,
        bh + oE0, bl + oE0, enc_b0, nullptr, h1h, h1l, OUTC, N, INC, 1);
    gemm_cp<<<dim3(2, rowTiles), blk, GSMEM, s2>>>(h1h, h1l, OUTC, OUTC, nullptr, nullptr, 0,
        bh + oE1, bl + oE1, enc_b1, nullptr, h2h, h2l, OUTC, N, OUTC, 1);
    gemm_cp<<<dim3(1, rowTiles), blk, GSMEM, s2>>>(h2h, h2l, OUTC, OUTC, nullptr, nullptr, 0,
        bh + oE2, bl + oE2, enc_b2, out, nullptr, nullptr, OUTC, N, OUTC, 0);
    cudaEventRecord(evEnc, s2);

    // ===== main stream: CSR build, then conv branch =====
    cudaMemsetAsync(cnt, 0, (size_t)NB * sizeof(int));
    cudaMemsetAsync(cur, 0, (size_t)NB * sizeof(int));
    count_k<<<(E + 255) / 256, 256>>>(dst, etype, E, cnt);
    inv_k<<<(NB + 255) / 256, 256>>>(cnt, inv, NB);
    scan1_k<<<NBLK, 1024>>>(cnt, bsum);
    scan2_k<<<1, 128>>>(bsum, NBLK);
    scan3_k<<<NBLK, 1024>>>(cnt, bsum, off);
    fill_k<<<(E + 255) / 256, 256>>>(src, dst, etype, E, off, cur, csr);

    cudaStreamWaitEvent(0, evSplit, 0);  // agg1 needs xh/xl only

    // --- conv1: K = 896 ---
    agg_k<INC><<<(NN + 7) / 8, blk>>>(xh, xl, off, cnt, inv, csr, acch, accl);
    cudaStreamWaitEvent(0, evPrep, 0);   // gemm1 needs conv weights
    gemm_cp<<<dim3(2, rowTiles), blk, GSMEM>>>(xh, xl, INC, INC, acch, accl, NR * INC,
        bh + oC1, bl + oC1, b1, nullptr, g1h, g1l, OUTC, N, K1, 1);

    // --- conv2: K = 1792 ---
    agg_k<OUTC><<<(NN + 3) / 4, blk>>>(g1h, g1l, off, cnt, inv, csr, acch, accl);
    gemm_cp<<<dim3(2, rowTiles), blk, GSMEM>>>(g1h, g1l, OUTC, OUTC, acch, accl, NR * OUTC,
        bh + oC2, bl + oC2, b2, nullptr, g2h, g2l, OUTC, N, K2, 1);

    // --- conv3 -> out[:, 128:256] ---
    agg_k<OUTC><<<(NN + 3) / 4, blk>>>(g2h, g2l, off, cnt, inv, csr, acch, accl);
    gemm_cp<<<dim3(1, rowTiles), blk, GSMEM>>>(g2h, g2l, OUTC, OUTC, acch, accl, NR * OUTC,
        bh + oC3, bl + oC3, b3, out + HALF, nullptr, nullptr, OUTC, N, K2, 0);

    cudaStreamWaitEvent(0, evEnc, 0);    // join encoder branch before return
}

// round 15
// speedup vs baseline: 1.5719x; 1.5719x over previous
#include <cuda_runtime.h>
#include <cuda_bf16.h>
#include <cstdint>
#include <cstddef>

#define NN   50000
#define EE   800000
#define INC  128
#define OUTC 256
#define HALF 128
#define NR   6
#define NB   (NN * NR)            // 300000 buckets (node, rel)
#define NBLK ((NB + 4095) / 4096) // 74 scan blocks

// ---------------- scratch (module-scope device memory; no allocations) ------
__device__ __align__(16) __nv_bfloat16 d_xh [(size_t)NN * INC];
__device__ __align__(16) __nv_bfloat16 d_xl [(size_t)NN * INC];
__device__ __align__(16) __nv_bfloat16 d_h1h[(size_t)NN * OUTC];
__device__ __align__(16) __nv_bfloat16 d_h1l[(size_t)NN * OUTC];
__device__ __align__(16) __nv_bfloat16 d_h2h[(size_t)NN * OUTC];
__device__ __align__(16) __nv_bfloat16 d_h2l[(size_t)NN * OUTC];
__device__ __align__(16) __nv_bfloat16 d_g1h[(size_t)NN * OUTC];
__device__ __align__(16) __nv_bfloat16 d_g1l[(size_t)NN * OUTC];
__device__ __align__(16) __nv_bfloat16 d_g2h[(size_t)NN * OUTC];
__device__ __align__(16) __nv_bfloat16 d_g2l[(size_t)NN * OUTC];
__device__ __align__(16) __nv_bfloat16 d_acch[(size_t)NN * NR * OUTC];
__device__ __align__(16) __nv_bfloat16 d_accl[(size_t)NN * NR * OUTC];
__device__ int   d_cnt[NB];
__device__ int   d_off[NB];
__device__ int   d_cur[NB];
__device__ int   d_csr[EE];
__device__ int   d_bsum[128];
__device__ float d_inv[NB];
__device__ float d_wc1[(size_t)(NR + 1) * INC  * OUTC];
__device__ float d_wc2[(size_t)(NR + 1) * OUTC * OUTC];
__device__ float d_wc3[(size_t)(NR + 1) * OUTC * HALF];
__device__ __align__(16) __nv_bfloat16 d_bh[1048576];
__device__ __align__(16) __nv_bfloat16 d_bl[1048576];

// ---------------- helpers (sm_80+ family-wide; no sm_103a-only ISA) ---------
__device__ __forceinline__ uint32_t smem_u32(const void* p) {
    uint32_t a;
    asm("{ .reg .u64 t; cvta.to.shared.u64 t, %1; cvt.u32.u64 %0, t; }" : "=r"(a) : "l"(p));
    return a;
}
__device__ __forceinline__ void ldsm4(uint32_t* r, uint32_t addr) {
    asm volatile("ldmatrix.sync.aligned.m8n8.x4.shared.b16 {%0,%1,%2,%3}, [%4];"
        : "=r"(r[0]), "=r"(r[1]), "=r"(r[2]), "=r"(r[3]) : "r"(addr));
}
__device__ __forceinline__ void mma16816(float* c, const uint32_t* a, const uint32_t* b) {
    asm volatile("mma.sync.aligned.m16n8k16.row.col.f32.bf16.bf16.f32 "
        "{%0,%1,%2,%3}, {%4,%5,%6,%7}, {%8,%9}, {%0,%1,%2,%3};"
        : "+f"(c[0]), "+f"(c[1]), "+f"(c[2]), "+f"(c[3])
        : "r"(a[0]), "r"(a[1]), "r"(a[2]), "r"(a[3]), "r"(b[0]), "r"(b[1]));
}
#define CPA16(dst, src) \
    asm volatile("cp.async.cg.shared.global [%0], [%1], 16;" :: "r"(dst), "l"(src) : "memory")
#define CP_COMMIT()  asm volatile("cp.async.commit_group;" ::: "memory")
#define CP_WAIT1()   asm volatile("cp.async.wait_group 1;" ::: "memory")
#define CP_WAIT0()   asm volatile("cp.async.wait_group 0;" ::: "memory")

// ---------------- all-bf16 cp.async 3-stage bf16x3 GEMM ----------------------
#define STG 32768
#define GSMEM (3 * STG)

__global__ void __launch_bounds__(256, 2)
gemm_cp(const __nv_bfloat16* __restrict__ Ah0, const __nv_bfloat16* __restrict__ Al0,
        int d0, int ld0,
        const __nv_bfloat16* __restrict__ Ah1, const __nv_bfloat16* __restrict__ Al1,
        int ld1,
        const __nv_bfloat16* __restrict__ Bh, const __nv_bfloat16* __restrict__ Bl,
        const float* __restrict__ bias,
        float* __restrict__ Cf, __nv_bfloat16* __restrict__ Ch, __nv_bfloat16* __restrict__ Cl,
        int ldc, int M, int K, int relu)
{
    extern __shared__ char sm[];
    const uint32_t sb = smem_u32(sm);
    const int tid  = threadIdx.x;
    const int lane = tid & 31;
    const int w    = tid >> 5;
    const int wm   = w & 3;
    const int wn   = w >> 2;
    const int row0 = blockIdx.y * 128;
    const int n0   = blockIdx.x * 128;
    const int nIter = K / 32;

    float acc[2][8][4];
#pragma unroll
    for (int i = 0; i < 2; i++)
#pragma unroll
        for (int j = 0; j < 8; j++)
#pragma unroll
            for (int q = 0; q < 4; q++) acc[i][j][q] = 0.f;

    auto issue = [&](int s, uint32_t base) {
        int cb = s * 32;
        const __nv_bfloat16 *pAh, *pAl; int ld;
        if (cb < d0) { pAh = Ah0; pAl = Al0; ld = ld0; }
        else         { pAh = Ah1; pAl = Al1; ld = ld1; cb -= d0; }
#pragma unroll
        for (int j = 0; j < 2; j++) {
            int idx = tid + j * 256;              // 512 chunks (128 rows x 4)
            int r = idx >> 2, c = idx & 3;
            uint32_t so = (uint32_t)(r * 64 + ((c ^ ((r >> 1) & 3)) << 4));
            int gr = row0 + r; if (gr >= M) gr = M - 1;
            size_t ga = (size_t)gr * ld + cb + c * 8;
            CPA16(base + so,        pAh + ga);
            CPA16(base + 8192 + so, pAl + ga);
        }
        const int kb = s * 32;
#pragma unroll
        for (int j = 0; j < 2; j++) {
            int idx = tid + j * 256;
            int r = idx >> 2, c = idx & 3;
            uint32_t so = (uint32_t)(r * 64 + ((c ^ ((r >> 1) & 3)) << 4));
            size_t ga = (size_t)(n0 + r) * K + kb + c * 8;
            CPA16(base + 16384 + so, Bh + ga);
            CPA16(base + 24576 + so, Bl + ga);
        }
        CP_COMMIT();
    };

    issue(0, sb);
    if (nIter > 1) issue(1, sb + STG);

    const int aR   = lane & 15;
    const int aSwz = (lane >> 1) & 3;
    const int aCof = lane >> 4;
    const int bR   = (lane & 7) + ((lane >> 4) << 3);
    const int bSwz = (bR >> 1) & 3;
    const int bCof = (lane >> 3) & 1;

    int st = 0, stNxt = (nIter > 2) ? 2 : 0;
    for (int s = 0; s < nIter; s++) {
        if (s + 1 < nIter) CP_WAIT1(); else CP_WAIT0();
        __syncthreads();
        if (s + 2 < nIter) {
            issue(s + 2, sb + (uint32_t)stNxt * STG);
            stNxt = (stNxt + 1 == 3) ? 0 : stNxt + 1;
        }
        const uint32_t base = sb + (uint32_t)st * STG;
        st = (st + 1 == 3) ? 0 : st + 1;
#pragma unroll
        for (int kk = 0; kk < 32; kk += 16) {
            const int ckk = kk >> 3;
            uint32_t ah[2][4], al[2][4];
#pragma unroll
            for (int mi = 0; mi < 2; mi++) {
                int row = wm * 32 + mi * 16 + aR;
                uint32_t so = (uint32_t)(row * 64 + (((ckk + aCof) ^ aSwz) << 4));
                ldsm4(ah[mi], base + so);
                ldsm4(al[mi], base + 8192 + so);
            }
#pragma unroll
            for (int j2 = 0; j2 < 4; j2++) {
                int row = wn * 64 + j2 * 16 + bR;
                uint32_t so = (uint32_t)(row * 64 + (((ckk + bCof) ^ bSwz) << 4));
                uint32_t bhf[4], blf[4];
                ldsm4(bhf, base + 16384 + so);
                ldsm4(blf, base + 24576 + so);
#pragma unroll
                for (int mi = 0; mi < 2; mi++)
#pragma unroll
                    for (int nj = 0; nj < 2; nj++) {
                        float* c = acc[mi][j2 * 2 + nj];
                        mma16816(c, ah[mi], bhf + nj * 2);
                        mma16816(c, al[mi], bhf + nj * 2);
                        mma16816(c, ah[mi], blf + nj * 2);
                    }
            }
        }
    }

    // ---- epilogue ----
    const int g  = lane >> 2;
    const int tg = lane & 3;
#pragma unroll
    for (int mi = 0; mi < 2; mi++) {
        int r0 = row0 + wm * 32 + mi * 16 + g;
#pragma unroll
        for (int j = 0; j < 8; j++) {
            int gc = n0 + wn * 64 + j * 8 + tg * 2;
            float b0 = bias[gc], b1 = bias[gc + 1];
            float2 v0 = make_float2(acc[mi][j][0] + b0, acc[mi][j][1] + b1);
            float2 v1 = make_float2(acc[mi][j][2] + b0, acc[mi][j][3] + b1);
            if (relu) {
                v0.x = fmaxf(v0.x, 0.f); v0.y = fmaxf(v0.y, 0.f);
                v1.x = fmaxf(v1.x, 0.f); v1.y = fmaxf(v1.y, 0.f);
            }
#pragma unroll
            for (int h = 0; h < 2; h++) {
                int rr = r0 + h * 8;
                if (rr >= M) continue;
                float2 v = h ? v1 : v0;
                size_t o = (size_t)rr * ldc + gc;
                if (Cf) *(float2*)(Cf + o) = v;
                if (Ch) {
                    __nv_bfloat16 hx = __float2bfloat16(v.x), hy = __float2bfloat16(v.y);
                    __nv_bfloat162 hp = {hx, hy};
                    __nv_bfloat162 lp = {__float2bfloat16(v.x - __bfloat162float(hx)),
                                         __float2bfloat16(v.y - __bfloat162float(hy))};
                    *(__nv_bfloat162*)(Ch + o) = hp;
                    *(__nv_bfloat162*)(Cl + o) = lp;
                }
            }
        }
    }
}

// ---------------- fp32 -> bf16 hi/lo split (for x) ---------------------------
__global__ void split_k(const float* __restrict__ X, long n,
                        __nv_bfloat16* __restrict__ xh, __nv_bfloat16* __restrict__ xl)
{
    long i = blockIdx.x * (long)blockDim.x + threadIdx.x;
    if (i >= n) return;
    float v = X[i];
    __nv_bfloat16 hi = __float2bfloat16(v);
    xh[i] = hi;
    xl[i] = __float2bfloat16(v - __bfloat162float(hi));
}

// ---------------- weight convert: B fp32 [K][N] -> hi/lo bf16 [N][K] --------
__global__ void convw_k(const float* __restrict__ B, int K, int N,
                        __nv_bfloat16* __restrict__ bh, __nv_bfloat16* __restrict__ bl)
{
    int idx = blockIdx.x * blockDim.x + threadIdx.x;
    if (idx >= N * K) return;
    int n = idx / K, k = idx % K;
    float v = B[(size_t)k * N + n];
    __nv_bfloat16 hi = __float2bfloat16(v);
    bh[idx] = hi;
    bl[idx] = __float2bfloat16(v - __bfloat162float(hi));
}

// ---------------- (node,rel)-CSR build (proven) ------------------------------
__global__ void count_k(const int* __restrict__ dst, const int* __restrict__ et,
                        int E, int* __restrict__ cnt)
{
    int e = blockIdx.x * blockDim.x + threadIdx.x;
    if (e < E) atomicAdd(&cnt[dst[e] * NR + et[e]], 1);
}
__global__ void inv_k(const int* __restrict__ cnt, float* __restrict__ inv, int n)
{
    int i = blockIdx.x * blockDim.x + threadIdx.x;
    if (i < n) { int c = cnt[i]; inv[i] = 1.0f / (float)(c > 1 ? c : 1); }
}
__global__ void scan1_k(const int* __restrict__ cnt, int* __restrict__ bsum)
{
    __shared__ int sh[1024];
    int t = threadIdx.x;
    int i4 = blockIdx.x * 1024 + t;
    int s = 0;
    if (i4 * 4 < NB) {
        int4 v = ((const int4*)cnt)[i4];
        s = v.x + v.y + v.z + v.w;
    }
    sh[t] = s; __syncthreads();
    for (int o = 512; o > 0; o >>= 1) {
        if (t < o) sh[t] += sh[t + o];
        __syncthreads();
    }
    if (t == 0) bsum[blockIdx.x] = sh[0];
}
__global__ void scan2_k(int* __restrict__ bsum, int n)
{
    __shared__ int sh[128];
    int t = threadIdx.x;
    int v = (t < n) ? bsum[t] : 0;
    sh[t] = v; __syncthreads();
    for (int o = 1; o < 128; o <<= 1) {
        int u = (t >= o) ? sh[t - o] : 0;
        __syncthreads();
        sh[t] += u;
        __syncthreads();
    }
    if (t < n) bsum[t] = sh[t] - v;
}
__global__ void scan3_k(const int* __restrict__ cnt, const int* __restrict__ bsum,
                        int* __restrict__ off)
{
    __shared__ int sh[1024];
    int t = threadIdx.x;
    int i4 = blockIdx.x * 1024 + t;
    int4 v = make_int4(0, 0, 0, 0);
    bool ok = (i4 * 4 < NB);
    if (ok) v = ((const int4*)cnt)[i4];
    int s = v.x + v.y + v.z + v.w;
    sh[t] = s; __syncthreads();
    for (int o = 1; o < 1024; o <<= 1) {
        int u = (t >= o) ? sh[t - o] : 0;
        __syncthreads();
        sh[t] += u;
        __syncthreads();
    }
    int ex = bsum[blockIdx.x] + sh[t] - s;
    if (ok) {
        int4 w;
        w.x = ex;
        w.y = ex + v.x;
        w.z = ex + v.x + v.y;
        w.w = ex + v.x + v.y + v.z;
        ((int4*)off)[i4] = w;
    }
}
__global__ void fill_k(const int* __restrict__ src, const int* __restrict__ dst,
                       const int* __restrict__ et, int E,
                       const int* __restrict__ off, int* __restrict__ cur,
                       int* __restrict__ csr)
{
    int e = blockIdx.x * blockDim.x + threadIdx.x;
    if (e < E) {
        int k = dst[e] * NR + et[e];
        int p = off[k] + atomicAdd(&cur[k], 1);
        csr[p] = src[e];
    }
}

// ---------------- gather aggregation: bf16 hi/lo in, bf16 hi/lo out ----------
template<int D>
__global__ void __launch_bounds__(256)
agg_k(const __nv_bfloat16* __restrict__ xh, const __nv_bfloat16* __restrict__ xl,
      const int* __restrict__ off, const int* __restrict__ cnt,
      const float* __restrict__ inv, const int* __restrict__ csr,
      __nv_bfloat16* __restrict__ acch, __nv_bfloat16* __restrict__ accl)
{
    constexpr int T   = D / 4;
    constexpr int NPB = 256 / T;
    const int node = blockIdx.x * NPB + threadIdx.x / T;
    const int c4   = (threadIdx.x % T) * 4;
    if (node >= NN) return;
    const size_t base = (size_t)node * NR * D + c4;
#pragma unroll
    for (int r = 0; r < NR; r++) {
        const int b = node * NR + r;
        const int o = off[b], c = cnt[b];
        float a0 = 0.f, a1 = 0.f, a2 = 0.f, a3 = 0.f;
        int e = 0;
        for (; e + 2 <= c; e += 2) {
            int s0 = __ldg(&csr[o + e]);
            int s1 = __ldg(&csr[o + e + 1]);
            size_t p0 = (size_t)s0 * D + c4, p1 = (size_t)s1 * D + c4;
            uint2 h0 = __ldg((const uint2*)(xh + p0));
            uint2 l0 = __ldg((const uint2*)(xl + p0));
            uint2 h1 = __ldg((const uint2*)(xh + p1));
            uint2 l1 = __ldg((const uint2*)(xl + p1));
            float2 ha = __bfloat1622float2(*(__nv_bfloat162*)&h0.x);
            float2 hb = __bfloat1622float2(*(__nv_bfloat162*)&h0.y);
            float2 la = __bfloat1622float2(*(__nv_bfloat162*)&l0.x);
            float2 lb = __bfloat1622float2(*(__nv_bfloat162*)&l0.y);
            a0 += ha.x + la.x; a1 += ha.y + la.y; a2 += hb.x + lb.x; a3 += hb.y + lb.y;
            ha = __bfloat1622float2(*(__nv_bfloat162*)&h1.x);
            hb = __bfloat1622float2(*(__nv_bfloat162*)&h1.y);
            la = __bfloat1622float2(*(__nv_bfloat162*)&l1.x);
            lb = __bfloat1622float2(*(__nv_bfloat162*)&l1.y);
            a0 += ha.x + la.x; a1 += ha.y + la.y; a2 += hb.x + lb.x; a3 += hb.y + lb.y;
        }
        if (e < c) {
            int s0 = __ldg(&csr[o + e]);
            size_t p0 = (size_t)s0 * D + c4;
            uint2 h0 = __ldg((const uint2*)(xh + p0));
            uint2 l0 = __ldg((const uint2*)(xl + p0));
            float2 ha = __bfloat1622float2(*(__nv_bfloat162*)&h0.x);
            float2 hb = __bfloat1622float2(*(__nv_bfloat162*)&h0.y);
            float2 la = __bfloat1622float2(*(__nv_bfloat162*)&l0.x);
            float2 lb = __bfloat1622float2(*(__nv_bfloat162*)&l0.y);
            a0 += ha.x + la.x; a1 += ha.y + la.y; a2 += hb.x + lb.x; a3 += hb.y + lb.y;
        }
        const float m = inv[b];
        a0 *= m; a1 *= m; a2 *= m; a3 *= m;
        __nv_bfloat16 q0 = __float2bfloat16(a0), q1 = __float2bfloat16(a1);
        __nv_bfloat16 q2 = __float2bfloat16(a2), q3 = __float2bfloat16(a3);
        uint2 hv, lv;
        *(__nv_bfloat162*)&hv.x = {q0, q1};
        *(__nv_bfloat162*)&hv.y = {q2, q3};
        *(__nv_bfloat162*)&lv.x = {__float2bfloat16(a0 - __bfloat162float(q0)),
                                   __float2bfloat16(a1 - __bfloat162float(q1))};
        *(__nv_bfloat162*)&lv.y = {__float2bfloat16(a2 - __bfloat162float(q2)),
                                   __float2bfloat16(a3 - __bfloat162float(q3))};
        *(uint2*)(acch + base + r * D) = hv;
        *(uint2*)(accl + base + r * D) = lv;
    }
}

// ---------------- launch ------------------------------------------------------
extern "C" void kernel_launch(void* const* d_in, const int* in_sizes, int n_in,
                              void* d_out, int out_size)
{
    const float* x      = (const float*)d_in[0];
    const int*   eidx   = (const int*)  d_in[1];
    const int*   etype  = (const int*)  d_in[2];
    const float* enc_w0 = (const float*)d_in[3];
    const float* enc_b0 = (const float*)d_in[4];
    const float* enc_w1 = (const float*)d_in[5];
    const float* enc_b1 = (const float*)d_in[6];
    const float* enc_w2 = (const float*)d_in[7];
    const float* enc_b2 = (const float*)d_in[8];
    const float* W1     = (const float*)d_in[9];
    const float* root1  = (const float*)d_in[10];
    const float* b1     = (const float*)d_in[11];
    const float* W2     = (const float*)d_in[12];
    const float* root2  = (const float*)d_in[13];
    const float* b2     = (const float*)d_in[14];
    const float* W3     = (const float*)d_in[15];
    const float* root3  = (const float*)d_in[16];
    const float* b3     = (const float*)d_in[17];
    float* out = (float*)d_out;

    const int N = NN, E = EE;
    const int* src = eidx;
    const int* dst = eidx + E;

    float *inv, *wc1, *wc2, *wc3;
    int *cnt, *off, *cur, *csr, *bsum;
    __nv_bfloat16 *bh, *bl, *xh, *xl, *h1h, *h1l, *h2h, *h2l;
    __nv_bfloat16 *g1h, *g1l, *g2h, *g2l, *acch, *accl;
    cudaGetSymbolAddress((void**)&xh,   d_xh);
    cudaGetSymbolAddress((void**)&xl,   d_xl);
    cudaGetSymbolAddress((void**)&h1h,  d_h1h);
    cudaGetSymbolAddress((void**)&h1l,  d_h1l);
    cudaGetSymbolAddress((void**)&h2h,  d_h2h);
    cudaGetSymbolAddress((void**)&h2l,  d_h2l);
    cudaGetSymbolAddress((void**)&g1h,  d_g1h);
    cudaGetSymbolAddress((void**)&g1l,  d_g1l);
    cudaGetSymbolAddress((void**)&g2h,  d_g2h);
    cudaGetSymbolAddress((void**)&g2l,  d_g2l);
    cudaGetSymbolAddress((void**)&acch, d_acch);
    cudaGetSymbolAddress((void**)&accl, d_accl);
    cudaGetSymbolAddress((void**)&cnt,  d_cnt);
    cudaGetSymbolAddress((void**)&off,  d_off);
    cudaGetSymbolAddress((void**)&cur,  d_cur);
    cudaGetSymbolAddress((void**)&csr,  d_csr);
    cudaGetSymbolAddress((void**)&bsum, d_bsum);
    cudaGetSymbolAddress((void**)&inv,  d_inv);
    cudaGetSymbolAddress((void**)&wc1,  d_wc1);
    cudaGetSymbolAddress((void**)&wc2,  d_wc2);
    cudaGetSymbolAddress((void**)&wc3,  d_wc3);
    cudaGetSymbolAddress((void**)&bh,   d_bh);
    cudaGetSymbolAddress((void**)&bl,   d_bl);

    cudaFuncSetAttribute(gemm_cp, cudaFuncAttributeMaxDynamicSharedMemorySize, GSMEM);
    cudaFuncSetAttribute(gemm_cp, cudaFuncAttributePreferredSharedMemoryCarveout, 100);

    const int K1 = (NR + 1) * INC;    // 896
    const int K2 = (NR + 1) * OUTC;   // 1792
    const size_t oE0 = 0;
    const size_t oE1 = oE0 + (size_t)OUTC * INC;
    const size_t oE2 = oE1 + (size_t)OUTC * OUTC;
    const size_t oC1 = oE2 + (size_t)HALF * OUTC;
    const size_t oC2 = oC1 + (size_t)OUTC * K1;
    const size_t oC3 = oC2 + (size_t)OUTC * K2;

    // ---- fork a second stream (capture-safe fork/join; leaked, <= few calls)
    cudaStream_t s2;
    cudaEvent_t evFork, evSplit, evPrep, evEnc;
    cudaStreamCreateWithFlags(&s2, cudaStreamNonBlocking);
    cudaEventCreateWithFlags(&evFork,  cudaEventDisableTiming);
    cudaEventCreateWithFlags(&evSplit, cudaEventDisableTiming);
    cudaEventCreateWithFlags(&evPrep,  cudaEventDisableTiming);
    cudaEventCreateWithFlags(&evEnc,   cudaEventDisableTiming);
    cudaEventRecord(evFork, 0);
    cudaStreamWaitEvent(s2, evFork, 0);

    const dim3 blk(256);
    const int rowTiles = (N + 127) / 128;   // 391

    // ===== stream B: x split first (agg1 dep), weight prep, encoder branch ==
    split_k<<<(int)(((long)N * INC + 255) / 256), 256, 0, s2>>>(x, (long)N * INC, xh, xl);
    cudaEventRecord(evSplit, s2);     // xh/xl ready (agg1 needs only this + CSR)

    cudaMemcpyAsync(wc1,               root1, (size_t)INC  * OUTC * 4,      cudaMemcpyDeviceToDevice, s2);
    cudaMemcpyAsync(wc1 + INC * OUTC,  W1,    (size_t)NR * INC  * OUTC * 4, cudaMemcpyDeviceToDevice, s2);
    cudaMemcpyAsync(wc2,               root2, (size_t)OUTC * OUTC * 4,      cudaMemcpyDeviceToDevice, s2);
    cudaMemcpyAsync(wc2 + OUTC * OUTC, W2,    (size_t)NR * OUTC * OUTC * 4, cudaMemcpyDeviceToDevice, s2);
    cudaMemcpyAsync(wc3,               root3, (size_t)OUTC * HALF * 4,      cudaMemcpyDeviceToDevice, s2);
    cudaMemcpyAsync(wc3 + OUTC * HALF, W3,    (size_t)NR * OUTC * HALF * 4, cudaMemcpyDeviceToDevice, s2);

    convw_k<<<(OUTC * INC  + 255) / 256, 256, 0, s2>>>(enc_w0, INC,  OUTC, bh + oE0, bl + oE0);
    convw_k<<<(OUTC * OUTC + 255) / 256, 256, 0, s2>>>(enc_w1, OUTC, OUTC, bh + oE1, bl + oE1);
    convw_k<<<(HALF * OUTC + 255) / 256, 256, 0, s2>>>(enc_w2, OUTC, HALF, bh + oE2, bl + oE2);
    convw_k<<<(OUTC * K1 + 255) / 256, 256, 0, s2>>>(wc1, K1, OUTC, bh + oC1, bl + oC1);
    convw_k<<<(OUTC * K2 + 255) / 256, 256, 0, s2>>>(wc2, K2, OUTC, bh + oC2, bl + oC2);
    convw_k<<<(HALF * K2 + 255) / 256, 256, 0, s2>>>(wc3, K2, HALF, bh + oC3, bl + oC3);
    cudaEventRecord(evPrep, s2);      // all bf16 weights ready

    gemm_cp<<<dim3(2, rowTiles), blk, GSMEM, s2>>>(xh, xl, INC, INC, nullptr, nullptr, 0,
        bh + oE0, bl + oE0, enc_b0, nullptr, h1h, h1l, OUTC, N, INC, 1);
    gemm_cp<<<dim3(2, rowTiles), blk, GSMEM, s2>>>(h1h, h1l, OUTC, OUTC, nullptr, nullptr, 0,
        bh + oE1, bl + oE1, enc_b1, nullptr, h2h, h2l, OUTC, N, OUTC, 1);
    gemm_cp<<<dim3(1, rowTiles), blk, GSMEM, s2>>>(h2h, h2l, OUTC, OUTC, nullptr, nullptr, 0,
        bh + oE2, bl + oE2, enc_b2, out, nullptr, nullptr, OUTC, N, OUTC, 0);
    cudaEventRecord(evEnc, s2);

    // ===== main stream: CSR build, then conv branch =====
    cudaMemsetAsync(cnt, 0, (size_t)NB * sizeof(int));
    cudaMemsetAsync(cur, 0, (size_t)NB * sizeof(int));
    count_k<<<(E + 255) / 256, 256>>>(dst, etype, E, cnt);
    inv_k<<<(NB + 255) / 256, 256>>>(cnt, inv, NB);
    scan1_k<<<NBLK, 1024>>>(cnt, bsum);
    scan2_k<<<1, 128>>>(bsum, NBLK);
    scan3_k<<<NBLK, 1024>>>(cnt, bsum, off);
    fill_k<<<(E + 255) / 256, 256>>>(src, dst, etype, E, off, cur, csr);

    cudaStreamWaitEvent(0, evSplit, 0);  // agg1 needs xh/xl only

    // --- conv1: K = 896 ---
    agg_k<INC><<<(NN + 7) / 8, blk>>>(xh, xl, off, cnt, inv, csr, acch, accl);
    cudaStreamWaitEvent(0, evPrep, 0);   // gemm1 needs conv weights
    gemm_cp<<<dim3(2, rowTiles), blk, GSMEM>>>(xh, xl, INC, INC, acch, accl, NR * INC,
        bh + oC1, bl + oC1, b1, nullptr, g1h, g1l, OUTC, N, K1, 1);

    // --- conv2: K = 1792 ---
    agg_k<OUTC><<<(NN + 3) / 4, blk>>>(g1h, g1l, off, cnt, inv, csr, acch, accl);
    gemm_cp<<<dim3(2, rowTiles), blk, GSMEM>>>(g1h, g1l, OUTC, OUTC, acch, accl, NR * OUTC,
        bh + oC2, bl + oC2, b2, nullptr, g2h, g2l, OUTC, N, K2, 1);

    // --- conv3 -> out[:, 128:256] ---
    agg_k<OUTC><<<(NN + 3) / 4, blk>>>(g2h, g2l, off, cnt, inv, csr, acch, accl);
    gemm_cp<<<dim3(1, rowTiles), blk, GSMEM>>>(g2h, g2l, OUTC, OUTC, acch, accl, NR * OUTC,
        bh + oC3, bl + oC3, b3, out + HALF, nullptr, nullptr, OUTC, N, K2, 0);

    cudaStreamWaitEvent(0, evEnc, 0);    // join encoder branch before return
}

// round 16
// speedup vs baseline: 1.6728x; 1.0642x over previous
#include <cuda_runtime.h>
#include <cuda_fp16.h>
#include <cstdint>
#include <cstddef>

#define NN   50000
#define EE   800000
#define INC  128
#define OUTC 256
#define HALF 128
#define NR   6
#define NB   (NN * NR)            // 300000 buckets (node, rel)
#define NBLK ((NB + 4095) / 4096) // 74 scan blocks

// ---------------- scratch (module-scope device memory; no allocations) ------
__device__ __align__(16) __half d_xh [(size_t)NN * INC];
__device__ __align__(16) __half d_xl [(size_t)NN * INC];
__device__ __align__(16) __half d_h1h[(size_t)NN * OUTC];
__device__ __align__(16) __half d_h1l[(size_t)NN * OUTC];
__device__ __align__(16) __half d_h2h[(size_t)NN * OUTC];
__device__ __align__(16) __half d_h2l[(size_t)NN * OUTC];
__device__ __align__(16) __half d_g1h[(size_t)NN * OUTC];
__device__ __align__(16) __half d_g1l[(size_t)NN * OUTC];
__device__ __align__(16) __half d_g2h[(size_t)NN * OUTC];
__device__ __align__(16) __half d_g2l[(size_t)NN * OUTC];
__device__ __align__(16) __half d_acch[(size_t)NN * NR * OUTC];
__device__ __align__(16) __half d_accl[(size_t)NN * NR * OUTC];
__device__ int   d_cnt[NB];
__device__ int   d_off[NB];
__device__ int   d_cur[NB];
__device__ int   d_csr[EE];
__device__ int   d_bsum[128];
__device__ float d_inv[NB];
__device__ float d_wc1[(size_t)(NR + 1) * INC  * OUTC];
__device__ float d_wc2[(size_t)(NR + 1) * OUTC * OUTC];
__device__ float d_wc3[(size_t)(NR + 1) * OUTC * HALF];
__device__ __align__(16) __half d_bh[1048576];

// ---------------- helpers (sm_80+ family-wide; no sm_103a-only ISA) ---------
__device__ __forceinline__ uint32_t smem_u32(const void* p) {
    uint32_t a;
    asm("{ .reg .u64 t; cvta.to.shared.u64 t, %1; cvt.u32.u64 %0, t; }" : "=r"(a) : "l"(p));
    return a;
}
__device__ __forceinline__ void ldsm4(uint32_t* r, uint32_t addr) {
    asm volatile("ldmatrix.sync.aligned.m8n8.x4.shared.b16 {%0,%1,%2,%3}, [%4];"
        : "=r"(r[0]), "=r"(r[1]), "=r"(r[2]), "=r"(r[3]) : "r"(addr));
}
__device__ __forceinline__ void mma16816(float* c, const uint32_t* a, const uint32_t* b) {
    asm volatile("mma.sync.aligned.m16n8k16.row.col.f32.f16.f16.f32 "
        "{%0,%1,%2,%3}, {%4,%5,%6,%7}, {%8,%9}, {%0,%1,%2,%3};"
        : "+f"(c[0]), "+f"(c[1]), "+f"(c[2]), "+f"(c[3])
        : "r"(a[0]), "r"(a[1]), "r"(a[2]), "r"(a[3]), "r"(b[0]), "r"(b[1]));
}
#define CPA16(dst, src) \
    asm volatile("cp.async.cg.shared.global [%0], [%1], 16;" :: "r"(dst), "l"(src) : "memory")
#define CP_COMMIT()  asm volatile("cp.async.commit_group;" ::: "memory")
#define CP_WAIT1()   asm volatile("cp.async.wait_group 1;" ::: "memory")
#define CP_WAIT0()   asm volatile("cp.async.wait_group 0;" ::: "memory")

// ---------------- fp16x2 cp.async 3-stage GEMM -------------------------------
// C = [A0 | A1] * B^T + bias; A pre-split fp16 hi/lo (repr err ~2^-23),
// B fp16 (2^-12; averages out over K -> measured rel_err 3.3e-4).
// Tile 128x128, 8 warps, BK=32, 3 stages.  Stage: Ah 8K | Al 8K | Bh 8K.
#define STG 24576
#define GSMEM (3 * STG)

__global__ void __launch_bounds__(256, 2)
gemm_cp(const __half* __restrict__ Ah0, const __half* __restrict__ Al0,
        int d0, int ld0,
        const __half* __restrict__ Ah1, const __half* __restrict__ Al1,
        int ld1,
        const __half* __restrict__ Bh,
        const float* __restrict__ bias,
        float* __restrict__ Cf, __half* __restrict__ Ch, __half* __restrict__ Cl,
        int ldc, int M, int K, int relu)
{
    extern __shared__ char sm[];
    const uint32_t sb = smem_u32(sm);
    const int tid  = threadIdx.x;
    const int lane = tid & 31;
    const int w    = tid >> 5;
    const int wm   = w & 3;
    const int wn   = w >> 2;
    const int row0 = blockIdx.y * 128;
    const int n0   = blockIdx.x * 128;
    const int nIter = K / 32;

    float acc[2][8][4];
#pragma unroll
    for (int i = 0; i < 2; i++)
#pragma unroll
        for (int j = 0; j < 8; j++)
#pragma unroll
            for (int q = 0; q < 4; q++) acc[i][j][q] = 0.f;

    auto issue = [&](int s, uint32_t base) {
        int cb = s * 32;
        const __half *pAh, *pAl; int ld;
        if (cb < d0) { pAh = Ah0; pAl = Al0; ld = ld0; }
        else         { pAh = Ah1; pAl = Al1; ld = ld1; cb -= d0; }
#pragma unroll
        for (int j = 0; j < 2; j++) {
            int idx = tid + j * 256;              // 512 chunks (128 rows x 4)
            int r = idx >> 2, c = idx & 3;
            uint32_t so = (uint32_t)(r * 64 + ((c ^ ((r >> 1) & 3)) << 4));
            int gr = row0 + r; if (gr >= M) gr = M - 1;
            size_t ga = (size_t)gr * ld + cb + c * 8;
            CPA16(base + so,        pAh + ga);
            CPA16(base + 8192 + so, pAl + ga);
        }
        const int kb = s * 32;
#pragma unroll
        for (int j = 0; j < 2; j++) {
            int idx = tid + j * 256;
            int r = idx >> 2, c = idx & 3;
            uint32_t so = (uint32_t)(r * 64 + ((c ^ ((r >> 1) & 3)) << 4));
            size_t ga = (size_t)(n0 + r) * K + kb + c * 8;
            CPA16(base + 16384 + so, Bh + ga);
        }
        CP_COMMIT();
    };

    issue(0, sb);
    if (nIter > 1) issue(1, sb + STG);

    const int aR   = lane & 15;
    const int aSwz = (lane >> 1) & 3;
    const int aCof = lane >> 4;
    const int bR   = (lane & 7) + ((lane >> 4) << 3);
    const int bSwz = (bR >> 1) & 3;
    const int bCof = (lane >> 3) & 1;

    int st = 0, stNxt = (nIter > 2) ? 2 : 0;
    for (int s = 0; s < nIter; s++) {
        if (s + 1 < nIter) CP_WAIT1(); else CP_WAIT0();
        __syncthreads();
        if (s + 2 < nIter) {
            issue(s + 2, sb + (uint32_t)stNxt * STG);
            stNxt = (stNxt + 1 == 3) ? 0 : stNxt + 1;
        }
        const uint32_t base = sb + (uint32_t)st * STG;
        st = (st + 1 == 3) ? 0 : st + 1;
#pragma unroll
        for (int kk = 0; kk < 32; kk += 16) {
            const int ckk = kk >> 3;
            uint32_t ah[2][4], al[2][4];
#pragma unroll
            for (int mi = 0; mi < 2; mi++) {
                int row = wm * 32 + mi * 16 + aR;
                uint32_t so = (uint32_t)(row * 64 + (((ckk + aCof) ^ aSwz) << 4));
                ldsm4(ah[mi], base + so);
                ldsm4(al[mi], base + 8192 + so);
            }
#pragma unroll
            for (int j2 = 0; j2 < 4; j2++) {
                int row = wn * 64 + j2 * 16 + bR;
                uint32_t so = (uint32_t)(row * 64 + (((ckk + bCof) ^ bSwz) << 4));
                uint32_t bhf[4];
                ldsm4(bhf, base + 16384 + so);
#pragma unroll
                for (int mi = 0; mi < 2; mi++)
#pragma unroll
                    for (int nj = 0; nj < 2; nj++) {
                        float* c = acc[mi][j2 * 2 + nj];
                        mma16816(c, ah[mi], bhf + nj * 2);
                        mma16816(c, al[mi], bhf + nj * 2);
                    }
            }
        }
    }

    // ---- epilogue ----
    const int g  = lane >> 2;
    const int tg = lane & 3;
#pragma unroll
    for (int mi = 0; mi < 2; mi++) {
        int r0 = row0 + wm * 32 + mi * 16 + g;
#pragma unroll
        for (int j = 0; j < 8; j++) {
            int gc = n0 + wn * 64 + j * 8 + tg * 2;
            float b0 = bias[gc], b1 = bias[gc + 1];
            float2 v0 = make_float2(acc[mi][j][0] + b0, acc[mi][j][1] + b1);
            float2 v1 = make_float2(acc[mi][j][2] + b0, acc[mi][j][3] + b1);
            if (relu) {
                v0.x = fmaxf(v0.x, 0.f); v0.y = fmaxf(v0.y, 0.f);
                v1.x = fmaxf(v1.x, 0.f); v1.y = fmaxf(v1.y, 0.f);
            }
#pragma unroll
            for (int h = 0; h < 2; h++) {
                int rr = r0 + h * 8;
                if (rr >= M) continue;
                float2 v = h ? v1 : v0;
                size_t o = (size_t)rr * ldc + gc;
                if (Cf) *(float2*)(Cf + o) = v;
                if (Ch) {
                    __half hx = __float2half(v.x), hy = __float2half(v.y);
                    __half2 hp = {hx, hy};
                    __half2 lp = {__float2half(v.x - __half2float(hx)),
                                  __float2half(v.y - __half2float(hy))};
                    *(__half2*)(Ch + o) = hp;
                    *(__half2*)(Cl + o) = lp;
                }
            }
        }
    }
}

// ---------------- fp32 -> fp16 hi/lo split (for x) ---------------------------
__global__ void split_k(const float* __restrict__ X, long n,
                        __half* __restrict__ xh, __half* __restrict__ xl)
{
    long i = blockIdx.x * (long)blockDim.x + threadIdx.x;
    if (i >= n) return;
    float v = X[i];
    __half hi = __float2half(v);
    xh[i] = hi;
    xl[i] = __float2half(v - __half2float(hi));
}

// ---------------- weight convert: B fp32 [K][N] -> fp16 [N][K] ---------------
__global__ void convw_k(const float* __restrict__ B, int K, int N,
                        __half* __restrict__ bh)
{
    int idx = blockIdx.x * blockDim.x + threadIdx.x;
    if (idx >= N * K) return;
    int n = idx / K, k = idx % K;
    bh[idx] = __float2half(B[(size_t)k * N + n]);
}

// ---------------- (node,rel)-CSR build (proven) ------------------------------
__global__ void count_k(const int* __restrict__ dst, const int* __restrict__ et,
                        int E, int* __restrict__ cnt)
{
    int e = blockIdx.x * blockDim.x + threadIdx.x;
    if (e < E) atomicAdd(&cnt[dst[e] * NR + et[e]], 1);
}
__global__ void inv_k(const int* __restrict__ cnt, float* __restrict__ inv, int n)
{
    int i = blockIdx.x * blockDim.x + threadIdx.x;
    if (i < n) { int c = cnt[i]; inv[i] = 1.0f / (float)(c > 1 ? c : 1); }
}
__global__ void scan1_k(const int* __restrict__ cnt, int* __restrict__ bsum)
{
    __shared__ int sh[1024];
    int t = threadIdx.x;
    int i4 = blockIdx.x * 1024 + t;
    int s = 0;
    if (i4 * 4 < NB) {
        int4 v = ((const int4*)cnt)[i4];
        s = v.x + v.y + v.z + v.w;
    }
    sh[t] = s; __syncthreads();
    for (int o = 512; o > 0; o >>= 1) {
        if (t < o) sh[t] += sh[t + o];
        __syncthreads();
    }
    if (t == 0) bsum[blockIdx.x] = sh[0];
}
__global__ void scan2_k(int* __restrict__ bsum, int n)
{
    __shared__ int sh[128];
    int t = threadIdx.x;
    int v = (t < n) ? bsum[t] : 0;
    sh[t] = v; __syncthreads();
    for (int o = 1; o < 128; o <<= 1) {
        int u = (t >= o) ? sh[t - o] : 0;
        __syncthreads();
        sh[t] += u;
        __syncthreads();
    }
    if (t < n) bsum[t] = sh[t] - v;
}
__global__ void scan3_k(const int* __restrict__ cnt, const int* __restrict__ bsum,
                        int* __restrict__ off)
{
    __shared__ int sh[1024];
    int t = threadIdx.x;
    int i4 = blockIdx.x * 1024 + t;
    int4 v = make_int4(0, 0, 0, 0);
    bool ok = (i4 * 4 < NB);
    if (ok) v = ((const int4*)cnt)[i4];
    int s = v.x + v.y + v.z + v.w;
    sh[t] = s; __syncthreads();
    for (int o = 1; o < 1024; o <<= 1) {
        int u = (t >= o) ? sh[t - o] : 0;
        __syncthreads();
        sh[t] += u;
        __syncthreads();
    }
    int ex = bsum[blockIdx.x] + sh[t] - s;
    if (ok) {
        int4 w;
        w.x = ex;
        w.y = ex + v.x;
        w.z = ex + v.x + v.y;
        w.w = ex + v.x + v.y + v.z;
        ((int4*)off)[i4] = w;
    }
}
__global__ void fill_k(const int* __restrict__ src, const int* __restrict__ dst,
                       const int* __restrict__ et, int E,
                       const int* __restrict__ off, int* __restrict__ cur,
                       int* __restrict__ csr)
{
    int e = blockIdx.x * blockDim.x + threadIdx.x;
    if (e < E) {
        int k = dst[e] * NR + et[e];
        int p = off[k] + atomicAdd(&cur[k], 1);
        csr[p] = src[e];
    }
}

// ---------------- gather aggregation: fp16 hi/lo in, fp16 hi/lo out ----------
template<int D>
__global__ void __launch_bounds__(256)
agg_k(const __half* __restrict__ xh, const __half* __restrict__ xl,
      const int* __restrict__ off, const int* __restrict__ cnt,
      const float* __restrict__ inv, const int* __restrict__ csr,
      __half* __restrict__ acch, __half* __restrict__ accl)
{
    constexpr int T   = D / 4;
    constexpr int NPB = 256 / T;
    const int node = blockIdx.x * NPB + threadIdx.x / T;
    const int c4   = (threadIdx.x % T) * 4;
    if (node >= NN) return;
    const size_t base = (size_t)node * NR * D + c4;
#pragma unroll
    for (int r = 0; r < NR; r++) {
        const int b = node * NR + r;
        const int o = off[b], c = cnt[b];
        float a0 = 0.f, a1 = 0.f, a2 = 0.f, a3 = 0.f;
        int e = 0;
        for (; e + 2 <= c; e += 2) {
            int s0 = __ldg(&csr[o + e]);
            int s1 = __ldg(&csr[o + e + 1]);
            size_t p0 = (size_t)s0 * D + c4, p1 = (size_t)s1 * D + c4;
            uint2 h0 = __ldg((const uint2*)(xh + p0));
            uint2 l0 = __ldg((const uint2*)(xl + p0));
            uint2 h1 = __ldg((const uint2*)(xh + p1));
            uint2 l1 = __ldg((const uint2*)(xl + p1));
            float2 ha = __half22float2(*(__half2*)&h0.x);
            float2 hb = __half22float2(*(__half2*)&h0.y);
            float2 la = __half22float2(*(__half2*)&l0.x);
            float2 lb = __half22float2(*(__half2*)&l0.y);
            a0 += ha.x + la.x; a1 += ha.y + la.y; a2 += hb.x + lb.x; a3 += hb.y + lb.y;
            ha = __half22float2(*(__half2*)&h1.x);
            hb = __half22float2(*(__half2*)&h1.y);
            la = __half22float2(*(__half2*)&l1.x);
            lb = __half22float2(*(__half2*)&l1.y);
            a0 += ha.x + la.x; a1 += ha.y + la.y; a2 += hb.x + lb.x; a3 += hb.y + lb.y;
        }
        if (e < c) {
            int s0 = __ldg(&csr[o + e]);
            size_t p0 = (size_t)s0 * D + c4;
            uint2 h0 = __ldg((const uint2*)(xh + p0));
            uint2 l0 = __ldg((const uint2*)(xl + p0));
            float2 ha = __half22float2(*(__half2*)&h0.x);
            float2 hb = __half22float2(*(__half2*)&h0.y);
            float2 la = __half22float2(*(__half2*)&l0.x);
            float2 lb = __half22float2(*(__half2*)&l0.y);
            a0 += ha.x + la.x; a1 += ha.y + la.y; a2 += hb.x + lb.x; a3 += hb.y + lb.y;
        }
        const float m = inv[b];
        a0 *= m; a1 *= m; a2 *= m; a3 *= m;
        __half q0 = __float2half(a0), q1 = __float2half(a1);
        __half q2 = __float2half(a2), q3 = __float2half(a3);
        uint2 hv, lv;
        *(__half2*)&hv.x = {q0, q1};
        *(__half2*)&hv.y = {q2, q3};
        *(__half2*)&lv.x = {__float2half(a0 - __half2float(q0)),
                            __float2half(a1 - __half2float(q1))};
        *(__half2*)&lv.y = {__float2half(a2 - __half2float(q2)),
                            __float2half(a3 - __half2float(q3))};
        *(uint2*)(acch + base + r * D) = hv;
        *(uint2*)(accl + base + r * D) = lv;
    }
}

// ---------------- launch ------------------------------------------------------
extern "C" void kernel_launch(void* const* d_in, const int* in_sizes, int n_in,
                              void* d_out, int out_size)
{
    const float* x      = (const float*)d_in[0];
    const int*   eidx   = (const int*)  d_in[1];
    const int*   etype  = (const int*)  d_in[2];
    const float* enc_w0 = (const float*)d_in[3];
    const float* enc_b0 = (const float*)d_in[4];
    const float* enc_w1 = (const float*)d_in[5];
    const float* enc_b1 = (const float*)d_in[6];
    const float* enc_w2 = (const float*)d_in[7];
    const float* enc_b2 = (const float*)d_in[8];
    const float* W1     = (const float*)d_in[9];
    const float* root1  = (const float*)d_in[10];
    const float* b1     = (const float*)d_in[11];
    const float* W2     = (const float*)d_in[12];
    const float* root2  = (const float*)d_in[13];
    const float* b2     = (const float*)d_in[14];
    const float* W3     = (const float*)d_in[15];
    const float* root3  = (const float*)d_in[16];
    const float* b3     = (const float*)d_in[17];
    float* out = (float*)d_out;

    const int N = NN, E = EE;
    const int* src = eidx;
    const int* dst = eidx + E;

    float *inv, *wc1, *wc2, *wc3;
    int *cnt, *off, *cur, *csr, *bsum;
    __half *bh, *xh, *xl, *h1h, *h1l, *h2h, *h2l;
    __half *g1h, *g1l, *g2h, *g2l, *acch, *accl;
    cudaGetSymbolAddress((void**)&xh,   d_xh);
    cudaGetSymbolAddress((void**)&xl,   d_xl);
    cudaGetSymbolAddress((void**)&h1h,  d_h1h);
    cudaGetSymbolAddress((void**)&h1l,  d_h1l);
    cudaGetSymbolAddress((void**)&h2h,  d_h2h);
    cudaGetSymbolAddress((void**)&h2l,  d_h2l);
    cudaGetSymbolAddress((void**)&g1h,  d_g1h);
    cudaGetSymbolAddress((void**)&g1l,  d_g1l);
    cudaGetSymbolAddress((void**)&g2h,  d_g2h);
    cudaGetSymbolAddress((void**)&g2l,  d_g2l);
    cudaGetSymbolAddress((void**)&acch, d_acch);
    cudaGetSymbolAddress((void**)&accl, d_accl);
    cudaGetSymbolAddress((void**)&cnt,  d_cnt);
    cudaGetSymbolAddress((void**)&off,  d_off);
    cudaGetSymbolAddress((void**)&cur,  d_cur);
    cudaGetSymbolAddress((void**)&csr,  d_csr);
    cudaGetSymbolAddress((void**)&bsum, d_bsum);
    cudaGetSymbolAddress((void**)&inv,  d_inv);
    cudaGetSymbolAddress((void**)&wc1,  d_wc1);
    cudaGetSymbolAddress((void**)&wc2,  d_wc2);
    cudaGetSymbolAddress((void**)&wc3,  d_wc3);
    cudaGetSymbolAddress((void**)&bh,   d_bh);

    cudaFuncSetAttribute(gemm_cp, cudaFuncAttributeMaxDynamicSharedMemorySize, GSMEM);
    cudaFuncSetAttribute(gemm_cp, cudaFuncAttributePreferredSharedMemoryCarveout, 100);

    const int K1 = (NR + 1) * INC;    // 896
    const int K2 = (NR + 1) * OUTC;   // 1792
    const size_t oE0 = 0;
    const size_t oE1 = oE0 + (size_t)OUTC * INC;
    const size_t oE2 = oE1 + (size_t)OUTC * OUTC;
    const size_t oC1 = oE2 + (size_t)HALF * OUTC;
    const size_t oC2 = oC1 + (size_t)OUTC * K1;
    const size_t oC3 = oC2 + (size_t)OUTC * K2;

    // ---- fork a second stream (capture-safe fork/join; leaked, <= few calls)
    cudaStream_t s2;
    cudaEvent_t evFork, evSplit, evPrep, evEnc;
    cudaStreamCreateWithFlags(&s2, cudaStreamNonBlocking);
    cudaEventCreateWithFlags(&evFork,  cudaEventDisableTiming);
    cudaEventCreateWithFlags(&evSplit, cudaEventDisableTiming);
    cudaEventCreateWithFlags(&evPrep,  cudaEventDisableTiming);
    cudaEventCreateWithFlags(&evEnc,   cudaEventDisableTiming);
    cudaEventRecord(evFork, 0);
    cudaStreamWaitEvent(s2, evFork, 0);

    const dim3 blk(256);
    const int rowTiles = (N + 127) / 128;   // 391

    // ===== stream B: x split first (agg1 dep), weight prep, encoder branch ==
    split_k<<<(int)(((long)N * INC + 255) / 256), 256, 0, s2>>>(x, (long)N * INC, xh, xl);
    cudaEventRecord(evSplit, s2);     // xh/xl ready (agg1 needs only this + CSR)

    cudaMemcpyAsync(wc1,               root1, (size_t)INC  * OUTC * 4,      cudaMemcpyDeviceToDevice, s2);
    cudaMemcpyAsync(wc1 + INC * OUTC,  W1,    (size_t)NR * INC  * OUTC * 4, cudaMemcpyDeviceToDevice, s2);
    cudaMemcpyAsync(wc2,               root2, (size_t)OUTC * OUTC * 4,      cudaMemcpyDeviceToDevice, s2);
    cudaMemcpyAsync(wc2 + OUTC * OUTC, W2,    (size_t)NR * OUTC * OUTC * 4, cudaMemcpyDeviceToDevice, s2);
    cudaMemcpyAsync(wc3,               root3, (size_t)OUTC * HALF * 4,      cudaMemcpyDeviceToDevice, s2);
    cudaMemcpyAsync(wc3 + OUTC * HALF, W3,    (size_t)NR * OUTC * HALF * 4, cudaMemcpyDeviceToDevice, s2);

    convw_k<<<(OUTC * INC  + 255) / 256, 256, 0, s2>>>(enc_w0, INC,  OUTC, bh + oE0);
    convw_k<<<(OUTC * OUTC + 255) / 256, 256, 0, s2>>>(enc_w1, OUTC, OUTC, bh + oE1);
    convw_k<<<(HALF * OUTC + 255) / 256, 256, 0, s2>>>(enc_w2, OUTC, HALF, bh + oE2);
    convw_k<<<(OUTC * K1 + 255) / 256, 256, 0, s2>>>(wc1, K1, OUTC, bh + oC1);
    convw_k<<<(OUTC * K2 + 255) / 256, 256, 0, s2>>>(wc2, K2, OUTC, bh + oC2);
    convw_k<<<(HALF * K2 + 255) / 256, 256, 0, s2>>>(wc3, K2, HALF, bh + oC3);
    cudaEventRecord(evPrep, s2);      // all fp16 weights ready

    gemm_cp<<<dim3(2, rowTiles), blk, GSMEM, s2>>>(xh, xl, INC, INC, nullptr, nullptr, 0,
        bh + oE0, enc_b0, nullptr, h1h, h1l, OUTC, N, INC, 1);
    gemm_cp<<<dim3(2, rowTiles), blk, GSMEM, s2>>>(h1h, h1l, OUTC, OUTC, nullptr, nullptr, 0,
        bh + oE1, enc_b1, nullptr, h2h, h2l, OUTC, N, OUTC, 1);
    gemm_cp<<<dim3(1, rowTiles), blk, GSMEM, s2>>>(h2h, h2l, OUTC, OUTC, nullptr, nullptr, 0,
        bh + oE2, enc_b2, out, nullptr, nullptr, OUTC, N, OUTC, 0);
    cudaEventRecord(evEnc, s2);

    // ===== main stream: CSR build, then conv branch =====
    cudaMemsetAsync(cnt, 0, (size_t)NB * sizeof(int));
    cudaMemsetAsync(cur, 0, (size_t)NB * sizeof(int));
    count_k<<<(E + 255) / 256, 256>>>(dst, etype, E, cnt);
    inv_k<<<(NB + 255) / 256, 256>>>(cnt, inv, NB);
    scan1_k<<<NBLK, 1024>>>(cnt, bsum);
    scan2_k<<<1, 128>>>(bsum, NBLK);
    scan3_k<<<NBLK, 1024>>>(cnt, bsum, off);
    fill_k<<<(E + 255) / 256, 256>>>(src, dst, etype, E, off, cur, csr);

    cudaStreamWaitEvent(0, evSplit, 0);  // agg1 needs xh/xl only

    // --- conv1: K = 896 ---
    agg_k<INC><<<(NN + 7) / 8, blk>>>(xh, xl, off, cnt, inv, csr, acch, accl);
    cudaStreamWaitEvent(0, evPrep, 0);   // gemm1 needs conv weights
    gemm_cp<<<dim3(2, rowTiles), blk, GSMEM>>>(xh, xl, INC, INC, acch, accl, NR * INC,
        bh + oC1, b1, nullptr, g1h, g1l, OUTC, N, K1, 1);

    // --- conv2: K = 1792 ---
    agg_k<OUTC><<<(NN + 3) / 4, blk>>>(g1h, g1l, off, cnt, inv, csr, acch, accl);
    gemm_cp<<<dim3(2, rowTiles), blk, GSMEM>>>(g1h, g1l, OUTC, OUTC, acch, accl, NR * OUTC,
        bh + oC2, b2, nullptr, g2h, g2l, OUTC, N, K2, 1);

    // --- conv3 -> out[:, 128:256] ---
    agg_k<OUTC><<<(NN + 3) / 4, blk>>>(g2h, g2l, off, cnt, inv, csr, acch, accl);
    gemm_cp<<<dim3(1, rowTiles), blk, GSMEM>>>(g2h, g2l, OUTC, OUTC, acch, accl, NR * OUTC,
        bh + oC3, b3, out + HALF, nullptr, nullptr, OUTC, N, K2, 0);

    cudaStreamWaitEvent(0, evEnc, 0);    // join encoder branch before return
}